// round 14
// baseline (speedup 1.0000x reference)
#include <cuda_runtime.h>
#include <cuda_bf16.h>
#include <cstdint>

// MultiLayerGAT: 2-layer GAT, N=50000, E=800000 (+N self loops),
// IN_F=128, HEADS=4, HID=64 -> F_OUT=256, leaky_relu(0.2) attention,
// segment softmax by dst (max-free single pass), relu.
// edge_index arrives as int32 (JAX x64 disabled).
// Round 14 (3rd attempt at the 2-CTA/SM GEMM; rounds 12/13 hit infra
// failures): GEMM CTA 128x64 / 256 threads, __launch_bounds__(256,2) ->
// 2 CTAs/SM so barriers of one block overlap MMAs of the other.
// Pre-split bf16 operands + fused alpha epilogue; warp-per-node agg.

#define N_NODES 50000
#define N_EDGES 800000
#define EP      (N_EDGES + N_NODES)
#define F_OUT   256
#define HID     64
#define NEG     0.2f
#define NBLK_SCAN ((N_NODES + 255) / 256)   // 196
#define MPAD    50048                        // 391 * 128
#define NXW     (N_NODES * 64)

// ---------------- scratch ----------------
__device__ float    g_hfeat[(size_t)N_NODES * F_OUT];
__device__ float    g_alpha[(size_t)N_NODES * 8];       // [n][0..3]=src,[4..7]=dst
__device__ uint32_t g_xh[(size_t)MPAD * 64];
__device__ uint32_t g_xl[(size_t)MPAD * 64];
__device__ uint32_t g_h2h[(size_t)MPAD * 128];
__device__ uint32_t g_h2l[(size_t)MPAD * 128];
__device__ uint32_t g_w1h[64 * 256],  g_w1l[64 * 256];
__device__ uint32_t g_w2h[128 * 256], g_w2l[128 * 256];
__device__ int g_deg[N_NODES];
__device__ int g_off[N_NODES + 1];
__device__ int g_cursor[N_NODES];
__device__ int g_bsum[NBLK_SCAN];
__device__ int g_esrc[EP];

// ---------------- helpers ----------------
__device__ __forceinline__ void bf16_split2(float x0, float x1,
                                            uint32_t& hi, uint32_t& lo) {
    __nv_bfloat162 h = __floats2bfloat162_rn(x0, x1);
    float h0 = __bfloat162float(h.x), h1 = __bfloat162float(h.y);
    __nv_bfloat162 l = __floats2bfloat162_rn(x0 - h0, x1 - h1);
    hi = *reinterpret_cast<uint32_t*>(&h);
    lo = *reinterpret_cast<uint32_t*>(&l);
}

__device__ __forceinline__ void mma_bf16(float c[4], uint32_t a0, uint32_t a1,
                                         uint32_t a2, uint32_t a3,
                                         uint32_t b0, uint32_t b1) {
    asm volatile(
        "mma.sync.aligned.m16n8k16.row.col.f32.bf16.bf16.f32 "
        "{%0,%1,%2,%3}, {%4,%5,%6,%7}, {%8,%9}, {%0,%1,%2,%3};"
        : "+f"(c[0]), "+f"(c[1]), "+f"(c[2]), "+f"(c[3])
        : "r"(a0), "r"(a1), "r"(a2), "r"(a3), "r"(b0), "r"(b1));
}

// ---------------- prep / conv ----------------
__global__ void k_prep() {
    int i = blockIdx.x * 256 + threadIdx.x;
    if (i < N_NODES * 8) g_alpha[i] = 0.f;
    if (i < N_NODES) g_deg[i] = 1;
}

__global__ void k_zero_alpha() {
    int i = blockIdx.x * 256 + threadIdx.x;
    if (i < N_NODES * 8) g_alpha[i] = 0.f;
}

__global__ void k_conv(const float* __restrict__ x, const float* __restrict__ W1,
                       const float* __restrict__ W2) {
    int i = blockIdx.x * 256 + threadIdx.x;
    if (i < NXW) {
        int n = i >> 6, kp = i & 63;
        float2 v = *(const float2*)&x[(size_t)n * 128 + kp * 2];
        uint32_t hi, lo;
        bf16_split2(v.x, v.y, hi, lo);
        g_xh[(size_t)n * 64 + kp] = hi;
        g_xl[(size_t)n * 64 + kp] = lo;
        return;
    }
    int j = i - NXW;
    if (j < 64 * 256) {
        int kp = j >> 8, n = j & 255;
        uint32_t hi, lo;
        bf16_split2(W1[(kp * 2) * 256 + n], W1[(kp * 2 + 1) * 256 + n], hi, lo);
        g_w1h[j] = hi;
        g_w1l[j] = lo;
        return;
    }
    j -= 64 * 256;
    if (j < 128 * 256) {
        int kp = j >> 8, n = j & 255;
        uint32_t hi, lo;
        bf16_split2(W2[(kp * 2) * 256 + n], W2[(kp * 2 + 1) * 256 + n], hi, lo);
        g_w2h[j] = hi;
        g_w2l[j] = lo;
    }
}

// ---------------- CSR build ----------------
__global__ void k_hist(const int* __restrict__ ei) {
    int i = blockIdx.x * blockDim.x + threadIdx.x;
    if (i < N_EDGES) atomicAdd(&g_deg[ei[N_EDGES + i]], 1);
}

__global__ void k_scan_blk() {
    __shared__ int s[256];
    int i = blockIdx.x * 256 + threadIdx.x;
    int v = (i < N_NODES) ? g_deg[i] : 0;
    s[threadIdx.x] = v;
    __syncthreads();
    #pragma unroll
    for (int off = 1; off < 256; off <<= 1) {
        int t = (threadIdx.x >= off) ? s[threadIdx.x - off] : 0;
        __syncthreads();
        s[threadIdx.x] += t;
        __syncthreads();
    }
    if (i < N_NODES) g_off[i] = s[threadIdx.x];
    if (threadIdx.x == 255) g_bsum[blockIdx.x] = s[255];
}

__global__ void k_scan_top() {
    __shared__ int s[256];
    int t = threadIdx.x;
    int v = (t < NBLK_SCAN) ? g_bsum[t] : 0;
    s[t] = v;
    __syncthreads();
    #pragma unroll
    for (int off = 1; off < 256; off <<= 1) {
        int u = (t >= off) ? s[t - off] : 0;
        __syncthreads();
        s[t] += u;
        __syncthreads();
    }
    if (t < NBLK_SCAN) g_bsum[t] = s[t] - v;
}

__global__ void k_scan_add() {
    int i = blockIdx.x * 256 + threadIdx.x;
    if (i < N_NODES) {
        int excl = g_off[i] - g_deg[i] + g_bsum[blockIdx.x];
        g_off[i] = excl;
        g_cursor[i] = excl;
    }
    if (i == 0) g_off[N_NODES] = EP;
}

__global__ void k_scatter(const int* __restrict__ ei) {
    int i = blockIdx.x * blockDim.x + threadIdx.x;
    if (i < N_EDGES) {
        int s = ei[i];
        int d = ei[N_EDGES + i];
        int pos = atomicAdd(&g_cursor[d], 1);
        g_esrc[pos] = s;
    } else if (i < EP) {
        int n = i - N_EDGES;
        int pos = atomicAdd(&g_cursor[n], 1);
        g_esrc[pos] = n;
    }
}

// ---------------- bf16 3-term GEMM + fused alpha epilogue ----------------
// CTA tile 128x64, TBK=32 (16 kpairs), 256 threads = 8 warps (4m x 2n),
// warp tile 32x32 -> 2x4 m16n8k16 MMAs x 3 terms. 2 CTAs/SM.

#define TBM 128
#define TBN 64
#define KP  16
#define SPAD 8

__global__ __launch_bounds__(256, 2) void k_mm_split(
    const uint32_t* __restrict__ Ah, const uint32_t* __restrict__ Al,
    const uint32_t* __restrict__ Bh, const uint32_t* __restrict__ Bl,
    float* __restrict__ C, const float* __restrict__ a_src,
    const float* __restrict__ a_dst, int M, int KPtot) {
    __shared__ uint32_t Ahp[KP][TBM + SPAD];
    __shared__ uint32_t Alp[KP][TBM + SPAD];
    __shared__ uint32_t Bhp[KP][TBN + SPAD];
    __shared__ uint32_t Blp[KP][TBN + SPAD];

    int tid = threadIdx.x;
    int wid = tid >> 5, lane = tid & 31;
    int g = lane >> 2, tg = lane & 3;
    int warp_m = wid >> 1, warp_n = wid & 1;   // 4 x 2 warp grid
    int wm = warp_m * 32, wn = warp_n * 32;
    int m0 = blockIdx.y * TBM, n0 = blockIdx.x * TBN;

    // A: 512 uint4 slots over [128 rows x 16 kpairs]; 2 per thread
    int arow[2], awg[2];
    #pragma unroll
    for (int i = 0; i < 2; i++) {
        int idx = tid + i * 256;
        arow[i] = idx >> 2;
        awg[i]  = (idx & 3) * 4;
    }
    // B: 256 uint4 slots over [16 kp x 64 cols]; 1 per thread
    int bkp = tid >> 4;
    int bcc = (tid & 15) * 4;

    float acc[2][4][4];
    #pragma unroll
    for (int i = 0; i < 2; i++)
        #pragma unroll
        for (int j = 0; j < 4; j++)
            #pragma unroll
            for (int r = 0; r < 4; r++) acc[i][j][r] = 0.f;

    uint4 pah[2], pal[2], pbh, pbl;
    #pragma unroll
    for (int i = 0; i < 2; i++) {
        pah[i] = *(const uint4*)(Ah + (size_t)(m0 + arow[i]) * KPtot + awg[i]);
        pal[i] = *(const uint4*)(Al + (size_t)(m0 + arow[i]) * KPtot + awg[i]);
    }
    pbh = *(const uint4*)(Bh + (size_t)bkp * 256 + n0 + bcc);
    pbl = *(const uint4*)(Bl + (size_t)bkp * 256 + n0 + bcc);

    for (int kp0 = 0; kp0 < KPtot; kp0 += KP) {
        #pragma unroll
        for (int i = 0; i < 2; i++) {
            Ahp[awg[i] + 0][arow[i]] = pah[i].x;
            Ahp[awg[i] + 1][arow[i]] = pah[i].y;
            Ahp[awg[i] + 2][arow[i]] = pah[i].z;
            Ahp[awg[i] + 3][arow[i]] = pah[i].w;
            Alp[awg[i] + 0][arow[i]] = pal[i].x;
            Alp[awg[i] + 1][arow[i]] = pal[i].y;
            Alp[awg[i] + 2][arow[i]] = pal[i].z;
            Alp[awg[i] + 3][arow[i]] = pal[i].w;
        }
        *(uint4*)&Bhp[bkp][bcc] = pbh;
        *(uint4*)&Blp[bkp][bcc] = pbl;
        __syncthreads();

        int kpn = kp0 + KP;
        if (kpn < KPtot) {
            #pragma unroll
            for (int i = 0; i < 2; i++) {
                pah[i] = *(const uint4*)(Ah + (size_t)(m0 + arow[i]) * KPtot + kpn + awg[i]);
                pal[i] = *(const uint4*)(Al + (size_t)(m0 + arow[i]) * KPtot + kpn + awg[i]);
            }
            pbh = *(const uint4*)(Bh + (size_t)(kpn + bkp) * 256 + n0 + bcc);
            pbl = *(const uint4*)(Bl + (size_t)(kpn + bkp) * 256 + n0 + bcc);
        }

        #pragma unroll
        for (int kb = 0; kb < KP; kb += 8) {
            uint32_t ah[2][4], al[2][4], bh[4][2], bl[4][2];
            #pragma unroll
            for (int mt = 0; mt < 2; mt++) {
                int rm = wm + mt * 16;
                ah[mt][0] = Ahp[kb + tg][rm + g];
                ah[mt][1] = Ahp[kb + tg][rm + g + 8];
                ah[mt][2] = Ahp[kb + tg + 4][rm + g];
                ah[mt][3] = Ahp[kb + tg + 4][rm + g + 8];
                al[mt][0] = Alp[kb + tg][rm + g];
                al[mt][1] = Alp[kb + tg][rm + g + 8];
                al[mt][2] = Alp[kb + tg + 4][rm + g];
                al[mt][3] = Alp[kb + tg + 4][rm + g + 8];
            }
            #pragma unroll
            for (int nt = 0; nt < 4; nt++) {
                int cn = wn + nt * 8;
                bh[nt][0] = Bhp[kb + tg][cn + g];
                bh[nt][1] = Bhp[kb + tg + 4][cn + g];
                bl[nt][0] = Blp[kb + tg][cn + g];
                bl[nt][1] = Blp[kb + tg + 4][cn + g];
            }
            #pragma unroll
            for (int mt = 0; mt < 2; mt++)
                #pragma unroll
                for (int nt = 0; nt < 4; nt++) {
                    mma_bf16(acc[mt][nt], ah[mt][0], ah[mt][1], ah[mt][2], ah[mt][3],
                             bh[nt][0], bh[nt][1]);
                    mma_bf16(acc[mt][nt], ah[mt][0], ah[mt][1], ah[mt][2], ah[mt][3],
                             bl[nt][0], bl[nt][1]);
                    mma_bf16(acc[mt][nt], al[mt][0], al[mt][1], al[mt][2], al[mt][3],
                             bh[nt][0], bh[nt][1]);
                }
        }
        __syncthreads();
    }

    // epilogue: store C + fused alpha dot (head = global col window / 64)
    int head = (n0 + wn) >> 6;
    #pragma unroll
    for (int mt = 0; mt < 2; mt++) {
        float sr0 = 0.f, dr0 = 0.f, sr1 = 0.f, dr1 = 0.f;
        int gm0 = m0 + wm + mt * 16 + g;
        int gm1 = gm0 + 8;
        #pragma unroll
        for (int nt = 0; nt < 4; nt++) {
            int cn = n0 + wn + nt * 8 + tg * 2;
            float a0 = acc[mt][nt][0], a1 = acc[mt][nt][1];
            float a2 = acc[mt][nt][2], a3 = acc[mt][nt][3];
            float s0 = a_src[cn], s1 = a_src[cn + 1];
            float d0 = a_dst[cn], d1 = a_dst[cn + 1];
            sr0 += a0 * s0 + a1 * s1;  dr0 += a0 * d0 + a1 * d1;
            sr1 += a2 * s0 + a3 * s1;  dr1 += a2 * d0 + a3 * d1;
            if (gm0 < M) *(float2*)&C[(size_t)gm0 * F_OUT + cn] = make_float2(a0, a1);
            if (gm1 < M) *(float2*)&C[(size_t)gm1 * F_OUT + cn] = make_float2(a2, a3);
        }
        sr0 += __shfl_down_sync(0xffffffffu, sr0, 2, 4);
        sr0 += __shfl_down_sync(0xffffffffu, sr0, 1, 4);
        dr0 += __shfl_down_sync(0xffffffffu, dr0, 2, 4);
        dr0 += __shfl_down_sync(0xffffffffu, dr0, 1, 4);
        sr1 += __shfl_down_sync(0xffffffffu, sr1, 2, 4);
        sr1 += __shfl_down_sync(0xffffffffu, sr1, 1, 4);
        dr1 += __shfl_down_sync(0xffffffffu, dr1, 2, 4);
        dr1 += __shfl_down_sync(0xffffffffu, dr1, 1, 4);
        if (tg == 0) {
            if (gm0 < M) {
                atomicAdd(&g_alpha[(size_t)gm0 * 8 + head], sr0);
                atomicAdd(&g_alpha[(size_t)gm0 * 8 + 4 + head], dr0);
            }
            if (gm1 < M) {
                atomicAdd(&g_alpha[(size_t)gm1 * 8 + head], sr1);
                atomicAdd(&g_alpha[(size_t)gm1 * 8 + 4 + head], dr1);
            }
        }
    }
}

// ---------------- warp-per-node softmax-aggregate + bias + relu ----------------
template <bool SPLIT>
__global__ __launch_bounds__(256) void k_agg_t(const float* __restrict__ h,
                                               const float* __restrict__ bias,
                                               float* __restrict__ outp,
                                               uint32_t* __restrict__ oh,
                                               uint32_t* __restrict__ ol) {
    int wid = threadIdx.x >> 5, lane = threadIdx.x & 31;
    int n = blockIdx.x * 8 + wid;
    if (n >= N_NODES) return;
    int head = lane >> 3;
    int beg = g_off[n], end = g_off[n + 1];
    float ad = g_alpha[(size_t)n * 8 + 4 + head];

    float4 acc0 = make_float4(0.f, 0.f, 0.f, 0.f);
    float4 acc1 = make_float4(0.f, 0.f, 0.f, 0.f);
    float wsum = 0.f;

    for (int j = beg; j < end; j++) {
        int s = g_esrc[j];
        float e = g_alpha[(size_t)s * 8 + head] + ad;
        e = (e > 0.f) ? e : NEG * e;
        float w = __expf(e);
        const float4* hp = (const float4*)(h + (size_t)s * F_OUT + lane * 8);
        float4 v0 = hp[0];
        float4 v1 = hp[1];
        acc0.x = fmaf(w, v0.x, acc0.x);
        acc0.y = fmaf(w, v0.y, acc0.y);
        acc0.z = fmaf(w, v0.z, acc0.z);
        acc0.w = fmaf(w, v0.w, acc0.w);
        acc1.x = fmaf(w, v1.x, acc1.x);
        acc1.y = fmaf(w, v1.y, acc1.y);
        acc1.z = fmaf(w, v1.z, acc1.z);
        acc1.w = fmaf(w, v1.w, acc1.w);
        wsum += w;
    }

    float inv = 1.f / (wsum + 1e-16f);
    const float4* bp = (const float4*)(bias + lane * 8);
    float4 b0 = bp[0], b1 = bp[1];
    float4 o0, o1;
    o0.x = fmaxf(fmaf(acc0.x, inv, b0.x), 0.f);
    o0.y = fmaxf(fmaf(acc0.y, inv, b0.y), 0.f);
    o0.z = fmaxf(fmaf(acc0.z, inv, b0.z), 0.f);
    o0.w = fmaxf(fmaf(acc0.w, inv, b0.w), 0.f);
    o1.x = fmaxf(fmaf(acc1.x, inv, b1.x), 0.f);
    o1.y = fmaxf(fmaf(acc1.y, inv, b1.y), 0.f);
    o1.z = fmaxf(fmaf(acc1.z, inv, b1.z), 0.f);
    o1.w = fmaxf(fmaf(acc1.w, inv, b1.w), 0.f);

    if (SPLIT) {
        uint4 hv, lv;
        bf16_split2(o0.x, o0.y, hv.x, lv.x);
        bf16_split2(o0.z, o0.w, hv.y, lv.y);
        bf16_split2(o1.x, o1.y, hv.z, lv.z);
        bf16_split2(o1.z, o1.w, hv.w, lv.w);
        *(uint4*)(oh + (size_t)n * 128 + lane * 4) = hv;
        *(uint4*)(ol + (size_t)n * 128 + lane * 4) = lv;
    } else {
        float4* op = (float4*)(outp + (size_t)n * F_OUT + lane * 8);
        op[0] = o0;
        op[1] = o1;
    }
}

// ---------------- launch ----------------
extern "C" void kernel_launch(void* const* d_in, const int* in_sizes, int n_in,
                              void* d_out, int out_size) {
    const float* x      = (const float*)d_in[0];
    const int*   ei     = (const int*)d_in[1];
    const float* W1     = (const float*)d_in[2];
    const float* a_src1 = (const float*)d_in[3];
    const float* a_dst1 = (const float*)d_in[4];
    const float* b1     = (const float*)d_in[5];
    const float* W2     = (const float*)d_in[6];
    const float* a_src2 = (const float*)d_in[7];
    const float* a_dst2 = (const float*)d_in[8];
    const float* b2     = (const float*)d_in[9];
    float* out = (float*)d_out;

    float*    hfeat; cudaGetSymbolAddress((void**)&hfeat, g_hfeat);
    uint32_t* xh;    cudaGetSymbolAddress((void**)&xh, g_xh);
    uint32_t* xl;    cudaGetSymbolAddress((void**)&xl, g_xl);
    uint32_t* h2h;   cudaGetSymbolAddress((void**)&h2h, g_h2h);
    uint32_t* h2l;   cudaGetSymbolAddress((void**)&h2l, g_h2l);
    uint32_t* w1h;   cudaGetSymbolAddress((void**)&w1h, g_w1h);
    uint32_t* w1l;   cudaGetSymbolAddress((void**)&w1l, g_w1l);
    uint32_t* w2h;   cudaGetSymbolAddress((void**)&w2h, g_w2h);
    uint32_t* w2l;   cudaGetSymbolAddress((void**)&w2l, g_w2l);

    dim3 ggrid(F_OUT / TBN, MPAD / TBM);   // 4 x 391
    int nwblk = (N_NODES + 7) / 8;
    int nconv = (NXW + 64 * 256 + 128 * 256 + 255) / 256;

    k_prep<<<(N_NODES * 8 + 255) / 256, 256>>>();
    k_conv<<<nconv, 256>>>(x, W1, W2);
    k_hist<<<(N_EDGES + 255) / 256, 256>>>(ei);
    // launch #4 (ncu capture window)
    k_mm_split<<<ggrid, 256>>>(xh, xl, w1h, w1l, hfeat, a_src1, a_dst1, N_NODES, 64);
    k_scan_blk<<<NBLK_SCAN, 256>>>();
    k_scan_top<<<1, 256>>>();
    k_scan_add<<<NBLK_SCAN, 256>>>();
    k_scatter<<<(EP + 255) / 256, 256>>>(ei);

    // layer 1 aggregate -> split bf16 input for layer 2
    k_agg_t<true><<<nwblk, 256>>>(hfeat, b1, nullptr, h2h, h2l);

    k_zero_alpha<<<(N_NODES * 8 + 255) / 256, 256>>>();
    k_mm_split<<<ggrid, 256>>>(h2h, h2l, w2h, w2l, hfeat, a_src2, a_dst2, N_NODES, 128);
    k_agg_t<false><<<nwblk, 256>>>(hfeat, b2, out, nullptr, nullptr);
}

// round 15
// speedup vs baseline: 1.0312x; 1.0312x over previous
#include <cuda_runtime.h>
#include <cuda_bf16.h>
#include <cstdint>

// MultiLayerGAT: 2-layer GAT, N=50000, E=800000 (+N self loops),
// IN_F=128, HEADS=4, HID=64 -> F_OUT=256, leaky_relu(0.2) attention,
// segment softmax by dst (max-free single pass), relu.
// edge_index arrives as int32 (JAX x64 disabled).
// Round 15: round-10 GEMM config (inline bf16 3-term split, 512thr, 128x128)
// + fused alpha epilogue (atomics); k_conv removed; agg edge loop unroll x2.

#define N_NODES 50000
#define N_EDGES 800000
#define EP      (N_EDGES + N_NODES)
#define F_OUT   256
#define HID     64
#define NEG     0.2f
#define NBLK_SCAN ((N_NODES + 255) / 256)   // 196

// ---------------- scratch ----------------
__device__ float g_hfeat[(size_t)N_NODES * F_OUT];
__device__ float g_x2[(size_t)N_NODES * F_OUT];
__device__ float g_alpha[(size_t)N_NODES * 8];   // [n][0..3]=src, [4..7]=dst
__device__ int   g_deg[N_NODES];
__device__ int   g_off[N_NODES + 1];
__device__ int   g_cursor[N_NODES];
__device__ int   g_bsum[NBLK_SCAN];
__device__ int   g_esrc[EP];

// ---------------- helpers ----------------
__device__ __forceinline__ void bf16_split2(float x0, float x1,
                                            uint32_t& hi, uint32_t& lo) {
    __nv_bfloat162 h = __floats2bfloat162_rn(x0, x1);
    float h0 = __bfloat162float(h.x), h1 = __bfloat162float(h.y);
    __nv_bfloat162 l = __floats2bfloat162_rn(x0 - h0, x1 - h1);
    hi = *reinterpret_cast<uint32_t*>(&h);
    lo = *reinterpret_cast<uint32_t*>(&l);
}

__device__ __forceinline__ void mma_bf16(float c[4], uint32_t a0, uint32_t a1,
                                         uint32_t a2, uint32_t a3,
                                         uint32_t b0, uint32_t b1) {
    asm volatile(
        "mma.sync.aligned.m16n8k16.row.col.f32.bf16.bf16.f32 "
        "{%0,%1,%2,%3}, {%4,%5,%6,%7}, {%8,%9}, {%0,%1,%2,%3};"
        : "+f"(c[0]), "+f"(c[1]), "+f"(c[2]), "+f"(c[3])
        : "r"(a0), "r"(a1), "r"(a2), "r"(a3), "r"(b0), "r"(b1));
}

// ---------------- prep: zero alpha + deg init ----------------
__global__ void k_prep() {
    int i = blockIdx.x * 256 + threadIdx.x;
    if (i < N_NODES * 8) g_alpha[i] = 0.f;
    if (i < N_NODES) g_deg[i] = 1;
}

__global__ void k_zero_alpha() {
    int i = blockIdx.x * 256 + threadIdx.x;
    if (i < N_NODES * 8) g_alpha[i] = 0.f;
}

// ---------------- CSR build ----------------
__global__ void k_hist(const int* __restrict__ ei) {
    int i = blockIdx.x * blockDim.x + threadIdx.x;
    if (i < N_EDGES) atomicAdd(&g_deg[ei[N_EDGES + i]], 1);
}

__global__ void k_scan_blk() {
    __shared__ int s[256];
    int i = blockIdx.x * 256 + threadIdx.x;
    int v = (i < N_NODES) ? g_deg[i] : 0;
    s[threadIdx.x] = v;
    __syncthreads();
    #pragma unroll
    for (int off = 1; off < 256; off <<= 1) {
        int t = (threadIdx.x >= off) ? s[threadIdx.x - off] : 0;
        __syncthreads();
        s[threadIdx.x] += t;
        __syncthreads();
    }
    if (i < N_NODES) g_off[i] = s[threadIdx.x];
    if (threadIdx.x == 255) g_bsum[blockIdx.x] = s[255];
}

__global__ void k_scan_top() {
    __shared__ int s[256];
    int t = threadIdx.x;
    int v = (t < NBLK_SCAN) ? g_bsum[t] : 0;
    s[t] = v;
    __syncthreads();
    #pragma unroll
    for (int off = 1; off < 256; off <<= 1) {
        int u = (t >= off) ? s[t - off] : 0;
        __syncthreads();
        s[t] += u;
        __syncthreads();
    }
    if (t < NBLK_SCAN) g_bsum[t] = s[t] - v;
}

__global__ void k_scan_add() {
    int i = blockIdx.x * 256 + threadIdx.x;
    if (i < N_NODES) {
        int excl = g_off[i] - g_deg[i] + g_bsum[blockIdx.x];
        g_off[i] = excl;
        g_cursor[i] = excl;
    }
    if (i == 0) g_off[N_NODES] = EP;
}

__global__ void k_scatter(const int* __restrict__ ei) {
    int i = blockIdx.x * blockDim.x + threadIdx.x;
    if (i < N_EDGES) {
        int s = ei[i];
        int d = ei[N_EDGES + i];
        int pos = atomicAdd(&g_cursor[d], 1);
        g_esrc[pos] = s;
    } else if (i < EP) {
        int n = i - N_EDGES;
        int pos = atomicAdd(&g_cursor[n], 1);
        g_esrc[pos] = n;
    }
}

// ---------------- bf16 3-term split GEMM + fused alpha epilogue ----------------
// C[M x 256] = A[M x K] * B[K x 256], fp32 inputs split inline:
// hi = bf16(x), lo = bf16(x - hi); A*B ~= Ah*Bh + Ah*Bl + Al*Bh.
// CTA 128x128, TBK=32 (16 kpairs), 512 threads = 16 warps (4m x 4n),
// warp tile 32x32. Epilogue stores C and accumulates alpha dots via atomics.

#define TBM 128
#define TBN 128
#define TBK 32
#define KP  (TBK / 2)
#define SPAD 8

__global__ __launch_bounds__(512, 1) void k_gemm_tc(
    const float* __restrict__ A, const float* __restrict__ B,
    float* __restrict__ C, const float* __restrict__ a_src,
    const float* __restrict__ a_dst, int M, int K) {
    __shared__ uint32_t Ahp[KP][TBM + SPAD];
    __shared__ uint32_t Alp[KP][TBM + SPAD];
    __shared__ uint32_t Bhp[KP][TBN + SPAD];
    __shared__ uint32_t Blp[KP][TBN + SPAD];

    int tid = threadIdx.x;
    int wid = tid >> 5, lane = tid & 31;
    int g = lane >> 2, tg = lane & 3;
    int warp_m = wid >> 2, warp_n = wid & 3;   // 4 x 4 warp grid
    int wm = warp_m * 32, wn = warp_n * 32;
    int m0 = blockIdx.y * TBM, n0 = blockIdx.x * TBN;

    // A load coords: 1024 float4 slots over [128 rows x 32 k]
    int arow[2], apr[2];
    bool aok[2];
    #pragma unroll
    for (int i = 0; i < 2; i++) {
        int idx = tid + i * 512;
        arow[i] = idx >> 3;
        apr[i] = (idx & 7) * 2;                // k-pair base (k = apr*2)
        aok[i] = (m0 + arow[i]) < M;
    }
    // B load coords: 512 slots over [16 kp x 128 cols], 2 k-rows per thread
    int brp = tid >> 5;
    int bcc = (tid & 31) * 4;

    float acc[2][4][4];
    #pragma unroll
    for (int i = 0; i < 2; i++)
        #pragma unroll
        for (int j = 0; j < 4; j++)
            #pragma unroll
            for (int r = 0; r < 4; r++) acc[i][j][r] = 0.f;

    // prologue: tile 0 into registers
    float4 pa[2], pb0, pb1;
    #pragma unroll
    for (int i = 0; i < 2; i++) {
        pa[i] = make_float4(0.f, 0.f, 0.f, 0.f);
        if (aok[i]) pa[i] = *(const float4*)&A[(size_t)(m0 + arow[i]) * K + apr[i] * 2];
    }
    pb0 = *(const float4*)&B[(size_t)(brp * 2) * F_OUT + n0 + bcc];
    pb1 = *(const float4*)&B[(size_t)(brp * 2 + 1) * F_OUT + n0 + bcc];

    for (int k0 = 0; k0 < K; k0 += TBK) {
        // stage prefetched regs -> SMEM (bf16 hi/lo split, k-pair packed)
        #pragma unroll
        for (int i = 0; i < 2; i++) {
            uint32_t h0, l0, h1, l1;
            bf16_split2(pa[i].x, pa[i].y, h0, l0);
            bf16_split2(pa[i].z, pa[i].w, h1, l1);
            Ahp[apr[i]][arow[i]] = h0;  Alp[apr[i]][arow[i]] = l0;
            Ahp[apr[i] + 1][arow[i]] = h1;  Alp[apr[i] + 1][arow[i]] = l1;
        }
        {
            uint32_t hb[4], lb[4];
            bf16_split2(pb0.x, pb1.x, hb[0], lb[0]);
            bf16_split2(pb0.y, pb1.y, hb[1], lb[1]);
            bf16_split2(pb0.z, pb1.z, hb[2], lb[2]);
            bf16_split2(pb0.w, pb1.w, hb[3], lb[3]);
            *(uint4*)&Bhp[brp][bcc] = make_uint4(hb[0], hb[1], hb[2], hb[3]);
            *(uint4*)&Blp[brp][bcc] = make_uint4(lb[0], lb[1], lb[2], lb[3]);
        }
        __syncthreads();

        // prefetch next tile (overlaps MMA stage)
        int kn = k0 + TBK;
        if (kn < K) {
            #pragma unroll
            for (int i = 0; i < 2; i++) {
                pa[i] = make_float4(0.f, 0.f, 0.f, 0.f);
                if (aok[i])
                    pa[i] = *(const float4*)&A[(size_t)(m0 + arow[i]) * K + kn + apr[i] * 2];
            }
            pb0 = *(const float4*)&B[(size_t)(kn + brp * 2) * F_OUT + n0 + bcc];
            pb1 = *(const float4*)&B[(size_t)(kn + brp * 2 + 1) * F_OUT + n0 + bcc];
        }

        // MMA: 2 k16 steps per tile
        #pragma unroll
        for (int kb = 0; kb < KP; kb += 8) {
            uint32_t ah[2][4], al[2][4], bh[4][2], bl[4][2];
            #pragma unroll
            for (int mt = 0; mt < 2; mt++) {
                int rm = wm + mt * 16;
                ah[mt][0] = Ahp[kb + tg][rm + g];
                ah[mt][1] = Ahp[kb + tg][rm + g + 8];
                ah[mt][2] = Ahp[kb + tg + 4][rm + g];
                ah[mt][3] = Ahp[kb + tg + 4][rm + g + 8];
                al[mt][0] = Alp[kb + tg][rm + g];
                al[mt][1] = Alp[kb + tg][rm + g + 8];
                al[mt][2] = Alp[kb + tg + 4][rm + g];
                al[mt][3] = Alp[kb + tg + 4][rm + g + 8];
            }
            #pragma unroll
            for (int nt = 0; nt < 4; nt++) {
                int cn = wn + nt * 8;
                bh[nt][0] = Bhp[kb + tg][cn + g];
                bh[nt][1] = Bhp[kb + tg + 4][cn + g];
                bl[nt][0] = Blp[kb + tg][cn + g];
                bl[nt][1] = Blp[kb + tg + 4][cn + g];
            }
            #pragma unroll
            for (int mt = 0; mt < 2; mt++)
                #pragma unroll
                for (int nt = 0; nt < 4; nt++) {
                    mma_bf16(acc[mt][nt], ah[mt][0], ah[mt][1], ah[mt][2], ah[mt][3],
                             bh[nt][0], bh[nt][1]);
                    mma_bf16(acc[mt][nt], ah[mt][0], ah[mt][1], ah[mt][2], ah[mt][3],
                             bl[nt][0], bl[nt][1]);
                    mma_bf16(acc[mt][nt], al[mt][0], al[mt][1], al[mt][2], al[mt][3],
                             bh[nt][0], bh[nt][1]);
                }
        }
        __syncthreads();
    }

    // epilogue: store C + fused alpha dot (head = global col window / 64)
    int head = (n0 + wn) >> 6;
    #pragma unroll
    for (int mt = 0; mt < 2; mt++) {
        float sr0 = 0.f, dr0 = 0.f, sr1 = 0.f, dr1 = 0.f;
        int gm0 = m0 + wm + mt * 16 + g;
        int gm1 = gm0 + 8;
        #pragma unroll
        for (int nt = 0; nt < 4; nt++) {
            int cn = n0 + wn + nt * 8 + tg * 2;
            float a0 = acc[mt][nt][0], a1 = acc[mt][nt][1];
            float a2 = acc[mt][nt][2], a3 = acc[mt][nt][3];
            float s0 = a_src[cn], s1 = a_src[cn + 1];
            float d0 = a_dst[cn], d1 = a_dst[cn + 1];
            sr0 += a0 * s0 + a1 * s1;  dr0 += a0 * d0 + a1 * d1;
            sr1 += a2 * s0 + a3 * s1;  dr1 += a2 * d0 + a3 * d1;
            if (gm0 < M) *(float2*)&C[(size_t)gm0 * F_OUT + cn] = make_float2(a0, a1);
            if (gm1 < M) *(float2*)&C[(size_t)gm1 * F_OUT + cn] = make_float2(a2, a3);
        }
        sr0 += __shfl_down_sync(0xffffffffu, sr0, 2, 4);
        sr0 += __shfl_down_sync(0xffffffffu, sr0, 1, 4);
        dr0 += __shfl_down_sync(0xffffffffu, dr0, 2, 4);
        dr0 += __shfl_down_sync(0xffffffffu, dr0, 1, 4);
        sr1 += __shfl_down_sync(0xffffffffu, sr1, 2, 4);
        sr1 += __shfl_down_sync(0xffffffffu, sr1, 1, 4);
        dr1 += __shfl_down_sync(0xffffffffu, dr1, 2, 4);
        dr1 += __shfl_down_sync(0xffffffffu, dr1, 1, 4);
        if (tg == 0) {
            if (gm0 < M) {
                atomicAdd(&g_alpha[(size_t)gm0 * 8 + head], sr0);
                atomicAdd(&g_alpha[(size_t)gm0 * 8 + 4 + head], dr0);
            }
            if (gm1 < M) {
                atomicAdd(&g_alpha[(size_t)gm1 * 8 + head], sr1);
                atomicAdd(&g_alpha[(size_t)gm1 * 8 + 4 + head], dr1);
            }
        }
    }
}

// ---------------- warp-per-node softmax-aggregate + bias + relu ----------------
// Edge loop unrolled x2 for MLP (independent esrc/alpha/h loads per pair).
__global__ __launch_bounds__(256) void k_agg(const float* __restrict__ h,
                                             const float* __restrict__ bias,
                                             float* __restrict__ outp) {
    int wid = threadIdx.x >> 5, lane = threadIdx.x & 31;
    int n = blockIdx.x * 8 + wid;
    if (n >= N_NODES) return;
    int head = lane >> 3;
    int beg = g_off[n], end = g_off[n + 1];
    float ad = g_alpha[(size_t)n * 8 + 4 + head];

    float4 acc0 = make_float4(0.f, 0.f, 0.f, 0.f);
    float4 acc1 = make_float4(0.f, 0.f, 0.f, 0.f);
    float wsum = 0.f;

    int j = beg;
    for (; j + 1 < end; j += 2) {
        int s0 = g_esrc[j];
        int s1 = g_esrc[j + 1];
        float e0 = g_alpha[(size_t)s0 * 8 + head] + ad;
        float e1 = g_alpha[(size_t)s1 * 8 + head] + ad;
        e0 = (e0 > 0.f) ? e0 : NEG * e0;
        e1 = (e1 > 0.f) ? e1 : NEG * e1;
        float w0 = __expf(e0);
        float w1 = __expf(e1);
        const float4* hp0 = (const float4*)(h + (size_t)s0 * F_OUT + lane * 8);
        const float4* hp1 = (const float4*)(h + (size_t)s1 * F_OUT + lane * 8);
        float4 u0 = hp0[0], u1 = hp0[1];
        float4 v0 = hp1[0], v1 = hp1[1];
        acc0.x = fmaf(w0, u0.x, acc0.x); acc0.y = fmaf(w0, u0.y, acc0.y);
        acc0.z = fmaf(w0, u0.z, acc0.z); acc0.w = fmaf(w0, u0.w, acc0.w);
        acc1.x = fmaf(w0, u1.x, acc1.x); acc1.y = fmaf(w0, u1.y, acc1.y);
        acc1.z = fmaf(w0, u1.z, acc1.z); acc1.w = fmaf(w0, u1.w, acc1.w);
        acc0.x = fmaf(w1, v0.x, acc0.x); acc0.y = fmaf(w1, v0.y, acc0.y);
        acc0.z = fmaf(w1, v0.z, acc0.z); acc0.w = fmaf(w1, v0.w, acc0.w);
        acc1.x = fmaf(w1, v1.x, acc1.x); acc1.y = fmaf(w1, v1.y, acc1.y);
        acc1.z = fmaf(w1, v1.z, acc1.z); acc1.w = fmaf(w1, v1.w, acc1.w);
        wsum += w0 + w1;
    }
    if (j < end) {
        int s = g_esrc[j];
        float e = g_alpha[(size_t)s * 8 + head] + ad;
        e = (e > 0.f) ? e : NEG * e;
        float w = __expf(e);
        const float4* hp = (const float4*)(h + (size_t)s * F_OUT + lane * 8);
        float4 u0 = hp[0], u1 = hp[1];
        acc0.x = fmaf(w, u0.x, acc0.x); acc0.y = fmaf(w, u0.y, acc0.y);
        acc0.z = fmaf(w, u0.z, acc0.z); acc0.w = fmaf(w, u0.w, acc0.w);
        acc1.x = fmaf(w, u1.x, acc1.x); acc1.y = fmaf(w, u1.y, acc1.y);
        acc1.z = fmaf(w, u1.z, acc1.z); acc1.w = fmaf(w, u1.w, acc1.w);
        wsum += w;
    }

    float inv = 1.f / (wsum + 1e-16f);
    const float4* bp = (const float4*)(bias + lane * 8);
    float4 b0 = bp[0], b1 = bp[1];
    float4 o0, o1;
    o0.x = fmaxf(fmaf(acc0.x, inv, b0.x), 0.f);
    o0.y = fmaxf(fmaf(acc0.y, inv, b0.y), 0.f);
    o0.z = fmaxf(fmaf(acc0.z, inv, b0.z), 0.f);
    o0.w = fmaxf(fmaf(acc0.w, inv, b0.w), 0.f);
    o1.x = fmaxf(fmaf(acc1.x, inv, b1.x), 0.f);
    o1.y = fmaxf(fmaf(acc1.y, inv, b1.y), 0.f);
    o1.z = fmaxf(fmaf(acc1.z, inv, b1.z), 0.f);
    o1.w = fmaxf(fmaf(acc1.w, inv, b1.w), 0.f);
    float4* op = (float4*)(outp + (size_t)n * F_OUT + lane * 8);
    op[0] = o0;
    op[1] = o1;
}

// ---------------- launch ----------------
extern "C" void kernel_launch(void* const* d_in, const int* in_sizes, int n_in,
                              void* d_out, int out_size) {
    const float* x      = (const float*)d_in[0];
    const int*   ei     = (const int*)d_in[1];
    const float* W1     = (const float*)d_in[2];
    const float* a_src1 = (const float*)d_in[3];
    const float* a_dst1 = (const float*)d_in[4];
    const float* b1     = (const float*)d_in[5];
    const float* W2     = (const float*)d_in[6];
    const float* a_src2 = (const float*)d_in[7];
    const float* a_dst2 = (const float*)d_in[8];
    const float* b2     = (const float*)d_in[9];
    float* out = (float*)d_out;

    float* hfeat; cudaGetSymbolAddress((void**)&hfeat, g_hfeat);
    float* x2;    cudaGetSymbolAddress((void**)&x2, g_x2);

    dim3 ggrid(F_OUT / TBN, (N_NODES + TBM - 1) / TBM);   // 2 x 391
    int nwblk = (N_NODES + 7) / 8;

    k_prep<<<(N_NODES * 8 + 255) / 256, 256>>>();
    k_hist<<<(N_EDGES + 255) / 256, 256>>>(ei);
    k_scan_blk<<<NBLK_SCAN, 256>>>();
    // launch #4 (ncu capture window)
    k_gemm_tc<<<ggrid, 512>>>(x, W1, hfeat, a_src1, a_dst1, N_NODES, 128);
    k_scan_top<<<1, 256>>>();
    k_scan_add<<<NBLK_SCAN, 256>>>();
    k_scatter<<<(EP + 255) / 256, 256>>>(ei);

    // layer 1 aggregate
    k_agg<<<nwblk, 256>>>(hfeat, b1, x2);

    k_zero_alpha<<<(N_NODES * 8 + 255) / 256, 256>>>();
    k_gemm_tc<<<ggrid, 512>>>(x2, W2, hfeat, a_src2, a_dst2, N_NODES, 256);
    k_agg<<<nwblk, 256>>>(hfeat, b2, out);
}